// round 11
// baseline (speedup 1.0000x reference)
#include <cuda_runtime.h>
#include <cstdint>

#define NN 100096
#define FF 64
#define EB 128   // edges per scatter block

// ---------------- scratch (device globals: no runtime allocation) ----------
__device__ float g_sum_pos[(size_t)NN * FF];
__device__ float g_sum_neg[(size_t)NN * FF];
__device__ float g_cnt_pos[NN];
__device__ float g_cnt_neg[NN];
__device__ float g_hb[136];                // hb_pos, hb_neg, y2_pos, y2_neg

__device__ __forceinline__ float wsum(float v) {
#pragma unroll
    for (int o = 16; o > 0; o >>= 1) v += __shfl_xor_sync(0xffffffffu, v, o);
    return v;
}

// packed f32x2 helpers (sm_103a)
__device__ __forceinline__ unsigned long long fma2(unsigned long long a,
                                                   unsigned long long b,
                                                   unsigned long long c) {
    unsigned long long d;
    asm("fma.rn.f32x2 %0, %1, %2, %3;" : "=l"(d) : "l"(a), "l"(b), "l"(c));
    return d;
}
__device__ __forceinline__ unsigned long long pack2(float v) {
    unsigned long long d;
    asm("mov.b64 %0, {%1, %1};" : "=l"(d) : "r"(__float_as_uint(v)));
    return d;
}
__device__ __forceinline__ float2 unpack2(unsigned long long a) {
    unsigned int lo, hi;
    asm("mov.b64 {%0, %1}, %2;" : "=r"(lo), "=r"(hi) : "l"(a));
    return make_float2(__uint_as_float(lo), __uint_as_float(hi));
}

// ---------------- bias: proj(expmap0(b, c=1)) ------------------------------
__global__ void bias_kernel(const float* __restrict__ bp, const float* __restrict__ bn) {
    int lane = threadIdx.x;
    if (lane >= 32) return;
    const float* bs[2] = {bp, bn};
#pragma unroll
    for (int i = 0; i < 2; ++i) {
        float u0 = bs[i][lane], u1 = bs[i][lane + 32];
        float nb = fmaxf(sqrtf(wsum(u0 * u0 + u1 * u1)), 1e-15f);
        float s = tanhf(nb) / nb;
        float v0 = u0 * s, v1 = u1 * s;
        float vn = fmaxf(sqrtf(wsum(v0 * v0 + v1 * v1)), 1e-15f);
        if (vn > 0.996f) { float p = 0.996f / vn; v0 *= p; v1 *= p; }
        g_hb[i * 64 + lane]      = v0;
        g_hb[i * 64 + 32 + lane] = v1;
        float y2 = wsum(v0 * v0 + v1 * v1);
        if (lane == 0) g_hb[128 + i] = y2;
    }
}

// ---------------- scatter: smem-staged indices, 16 threads/edge ------------
__global__ void scatter_kernel(const float* __restrict__ x,
                               const int* __restrict__ pei, const int* __restrict__ nei,
                               float* __restrict__ sp, float* __restrict__ sn,
                               float* __restrict__ cp, float* __restrict__ cn, int E) {
    __shared__ int s_src[EB], s_dst[EB];
    const int* ei = blockIdx.y ? nei : pei;
    float* sum = blockIdx.y ? sn : sp;
    float* cnt = blockIdx.y ? cn : cp;
    long base = (long)blockIdx.x * EB;
    int tid = threadIdx.x;
    if (tid < EB) {
        long e = base + tid;
        s_src[tid] = (e < E) ? ei[e] : -1;
    } else {
        long e = base + (tid - EB);
        s_dst[tid - EB] = (e < E) ? ei[(long)E + e] : -1;
    }
    __syncthreads();
    int ch = tid & 15, eg = tid >> 4;
#pragma unroll
    for (int it = 0; it < EB / 16; ++it) {
        int e = it * 16 + eg;
        int dst = s_dst[e];
        if (dst < 0) continue;
        int src = s_src[e];
        float4 v = *reinterpret_cast<const float4*>(x + (size_t)src * FF + ch * 4);
        float* a = sum + (size_t)dst * FF + ch * 4;
        asm volatile("red.global.add.v4.f32 [%0], {%1,%2,%3,%4};"
                     :: "l"(a), "f"(v.x), "f"(v.y), "f"(v.z), "f"(v.w) : "memory");
        if (ch == 0)
            asm volatile("red.global.add.f32 [%0], %1;" :: "l"(cnt + dst), "f"(1.0f) : "memory");
    }
}

// ---------------- fused GEMM + hyperbolic epilogue -------------------------
// block: 128 nodes x one branch (by=0 pos, by=1 neg), both matrices of the
// branch; writes out[node][by*64 : by*64+64] directly. No scratch round-trip.
// thread: og=tid&7 (8 outputs), ng=tid>>3 (4 nodes: 4*ng..4*ng+3)
__global__ void __launch_bounds__(256, 2)
fused_kernel(const float* __restrict__ x,
             const float* __restrict__ Wp,  const float* __restrict__ Wpc,
             const float* __restrict__ Wn,  const float* __restrict__ Wnc,
             float* __restrict__ out, int n) {
    extern __shared__ float sh[];
    float* sAa = sh;                    // [64][128] mean vectors (scaled)
    float* sAx = sh + 64 * 128;         // [64][128] x vectors
    float* sWa = sh + 2 * 64 * 128;     // [64][68]  W_agg transposed
    float* sWc = sWa + 64 * 68;         // [64][68]  W_cc transposed
    float* sPN = sWc + 64 * 68;         // [128] ||mean|| clipped
    float* sXN = sPN + 128;             // [128] ||x||    clipped

    int by = blockIdx.y;
    const float* Wagg = by ? Wn : Wp;
    const float* Wcc  = by ? Wnc : Wpc;
    const float* sums = by ? g_sum_neg : g_sum_pos;
    const float* cnts = by ? g_cnt_neg : g_cnt_pos;
    long node0 = (long)blockIdx.x * 128;
    int tid = threadIdx.x;

    // stage weights transposed: sW[k*68+o] = W[o*64+k]
#pragma unroll
    for (int p = 0; p < 16; ++p) {
        int idx = p * 256 + tid;
        int o = idx >> 6, k = idx & 63;
        sWa[k * 68 + o] = Wagg[o * 64 + k];
        sWc[k * 68 + o] = Wcc[o * 64 + k];
    }
    // stage inputs transposed (mean scaling folded in)
    {
        int nl = tid & 127, kc = tid >> 7;   // kc in {0,1}
        long gn = node0 + nl;
        bool ok = gn < n;
        long gc = ok ? gn : 0;
        float scale = 1.0f / fmaxf(cnts[gc], 1.0f);
        const float4* rowA = reinterpret_cast<const float4*>(sums + (size_t)gc * 64);
        const float4* rowX = reinterpret_cast<const float4*>(x + (size_t)gc * 64);
#pragma unroll
        for (int pk = 0; pk < 8; ++pk) {
            int k4 = kc + 2 * pk;
            float4 va = ok ? rowA[k4] : make_float4(0.f, 0.f, 0.f, 0.f);
            float4 vx = ok ? rowX[k4] : make_float4(0.f, 0.f, 0.f, 0.f);
            sAa[(4 * k4 + 0) * 128 + nl] = va.x * scale;
            sAa[(4 * k4 + 1) * 128 + nl] = va.y * scale;
            sAa[(4 * k4 + 2) * 128 + nl] = va.z * scale;
            sAa[(4 * k4 + 3) * 128 + nl] = va.w * scale;
            sAx[(4 * k4 + 0) * 128 + nl] = vx.x;
            sAx[(4 * k4 + 1) * 128 + nl] = vx.y;
            sAx[(4 * k4 + 2) * 128 + nl] = vx.z;
            sAx[(4 * k4 + 3) * 128 + nl] = vx.w;
        }
    }
    __syncthreads();

    // input norms (clipped): threads 0-127 -> xn, 128-255 -> pn
    {
        int nl = tid & 127;
        const float* src = (tid < 128) ? sAx : sAa;
        float acc = 0.f;
#pragma unroll
        for (int k = 0; k < 64; ++k) { float v = src[k * 128 + nl]; acc = fmaf(v, v, acc); }
        float* dst = (tid < 128) ? sXN : sPN;
        dst[nl] = fmaxf(sqrtf(acc), 1e-15f);
    }
    __syncthreads();

    int og = tid & 7, ng = tid >> 3;
    float hbv[8];
#pragma unroll
    for (int j = 0; j < 8; ++j) hbv[j] = g_hb[by * 64 + 8 * og + j];
    float y2 = g_hb[128 + by];

    unsigned long long accP[4][4], accC[4][4];
#pragma unroll
    for (int i = 0; i < 4; ++i)
#pragma unroll
        for (int j = 0; j < 4; ++j) { accP[i][j] = 0ull; accC[i][j] = 0ull; }

#pragma unroll 4
    for (int k = 0; k < 64; ++k) {
        float4 aa = *reinterpret_cast<const float4*>(&sAa[k * 128 + 4 * ng]);
        float4 ax = *reinterpret_cast<const float4*>(&sAx[k * 128 + 4 * ng]);
        ulonglong2 wa0 = *reinterpret_cast<const ulonglong2*>(&sWa[k * 68 + 8 * og]);
        ulonglong2 wa1 = *reinterpret_cast<const ulonglong2*>(&sWa[k * 68 + 8 * og + 4]);
        ulonglong2 wc0 = *reinterpret_cast<const ulonglong2*>(&sWc[k * 68 + 8 * og]);
        ulonglong2 wc1 = *reinterpret_cast<const ulonglong2*>(&sWc[k * 68 + 8 * og + 4]);
        float av[4] = {aa.x, aa.y, aa.z, aa.w};
        float xv[4] = {ax.x, ax.y, ax.z, ax.w};
#pragma unroll
        for (int i = 0; i < 4; ++i) {
            unsigned long long pa = pack2(av[i]);
            unsigned long long px = pack2(xv[i]);
            accP[i][0] = fma2(pa, wa0.x, accP[i][0]);
            accP[i][1] = fma2(pa, wa0.y, accP[i][1]);
            accP[i][2] = fma2(pa, wa1.x, accP[i][2]);
            accP[i][3] = fma2(pa, wa1.y, accP[i][3]);
            accC[i][0] = fma2(px, wc0.x, accC[i][0]);
            accC[i][1] = fma2(px, wc0.y, accC[i][1]);
            accC[i][2] = fma2(px, wc1.x, accC[i][2]);
            accC[i][3] = fma2(px, wc1.y, accC[i][3]);
        }
    }

    // in-register hyperbolic epilogue, one node at a time
#pragma unroll
    for (int i = 0; i < 4; ++i) {
        int node = 4 * ng + i;
        long gn = node0 + node;

        float mvP[8], mvC[8];
#pragma unroll
        for (int j = 0; j < 4; ++j) {
            float2 p = unpack2(accP[i][j]);
            float2 c = unpack2(accC[i][j]);
            mvP[2 * j] = p.x; mvP[2 * j + 1] = p.y;
            mvC[2 * j] = c.x; mvC[2 * j + 1] = c.y;
        }
        float ssP = 0.f, ssC = 0.f, dh = 0.f;
#pragma unroll
        for (int j = 0; j < 8; ++j) {
            ssP = fmaf(mvP[j], mvP[j], ssP);
            ssC = fmaf(mvC[j], mvC[j], ssC);
            dh  = fmaf(mvC[j], hbv[j], dh);
        }
        // reduce across the 8 og-lanes (lanes differ in bits 0..2)
#pragma unroll
        for (int o = 1; o < 8; o <<= 1) {
            ssP += __shfl_xor_sync(0xffffffffu, ssP, o);
            ssC += __shfl_xor_sync(0xffffffffu, ssC, o);
            dh  += __shfl_xor_sync(0xffffffffu, dh, o);
        }

        float pn = sPN[node], xn = sXN[node];
        float mnP = fmaxf(sqrtf(ssP), 1e-15f);
        float tP = tanhf(mnP / pn * atanhf(fminf(pn, 1.0f - 1e-7f)));
        float scP = fminf(tP, 0.996f) / mnP;

        float mnC = fmaxf(sqrtf(ssC), 1e-15f);
        float tC = tanhf(mnC / xn * atanhf(fminf(xn, 1.0f - 1e-7f)));
        float sn_ = fminf(tC, 0.996f);
        float scC = sn_ / mnC;

        float xy = scC * dh;
        float x2 = sn_ * sn_;
        float f1 = 1.0f + 2.0f * xy + y2;
        float f2 = 1.0f - x2;
        float den = fmaxf(1.0f + 2.0f * xy + x2 * y2, 1e-15f);
        float inv = 1.0f / den;
        float qsq = fmaxf(f1 * f1 * x2 + 2.0f * f1 * f2 * xy + f2 * f2 * y2, 0.0f) * (inv * inv);
        float qn = fmaxf(sqrtf(qsq), 1e-15f);
        float clip = (qn > 0.996f) ? (0.996f / qn) : 1.0f;
        float g1 = f1 * inv * clip;     // applied to s = mvC*scC
        float g2 = f2 * inv * clip;     // applied to hb

        if (gn < n) {
            float o8[8];
#pragma unroll
            for (int j = 0; j < 8; ++j)
                o8[j] = fmaf(mvP[j], scP, fmaf(mvC[j] * scC, g1, g2 * hbv[j]));
            float4* dst = reinterpret_cast<float4*>(out + gn * 128 + by * 64 + 8 * og);
            dst[0] = make_float4(o8[0], o8[1], o8[2], o8[3]);
            dst[1] = make_float4(o8[4], o8[5], o8[6], o8[7]);
        }
    }
}

// ---------------------------------------------------------------------------
extern "C" void kernel_launch(void* const* d_in, const int* in_sizes, int n_in,
                              void* d_out, int out_size) {
    const float* x   = (const float*)d_in[0];
    const float* Wp  = (const float*)d_in[1];
    const float* Wpc = (const float*)d_in[2];
    const float* bpc = (const float*)d_in[3];
    const float* Wn  = (const float*)d_in[4];
    const float* Wnc = (const float*)d_in[5];
    const float* bnc = (const float*)d_in[6];
    const int* pei   = (const int*)d_in[7];
    const int* nei   = (const int*)d_in[8];
    float* out = (float*)d_out;

    int n = in_sizes[0] / 64;
    int E = in_sizes[7] / 2;

    void *psum_p, *psum_n, *pcnt_p, *pcnt_n;
    cudaGetSymbolAddress(&psum_p, g_sum_pos);
    cudaGetSymbolAddress(&psum_n, g_sum_neg);
    cudaGetSymbolAddress(&pcnt_p, g_cnt_pos);
    cudaGetSymbolAddress(&pcnt_n, g_cnt_neg);
    cudaMemsetAsync(psum_p, 0, (size_t)n * 64 * sizeof(float));
    cudaMemsetAsync(psum_n, 0, (size_t)n * 64 * sizeof(float));
    cudaMemsetAsync(pcnt_p, 0, (size_t)n * sizeof(float));
    cudaMemsetAsync(pcnt_n, 0, (size_t)n * sizeof(float));

    bias_kernel<<<1, 32>>>(bpc, bnc);

    dim3 sgrid((E + EB - 1) / EB, 2);
    scatter_kernel<<<sgrid, 256>>>(x, pei, nei,
                                   (float*)psum_p, (float*)psum_n,
                                   (float*)pcnt_p, (float*)pcnt_n, E);

    // smem: 2*[64x128] + 2*[64x68] + 2*[128] floats = 101,376 B (2 blocks/SM)
    const int FSMEM = (2 * 64 * 128 + 2 * 64 * 68 + 256) * (int)sizeof(float);
    cudaFuncSetAttribute(fused_kernel, cudaFuncAttributeMaxDynamicSharedMemorySize, FSMEM);
    dim3 fgrid((n + 127) / 128, 2);
    fused_kernel<<<fgrid, 256, FSMEM>>>(x, Wp, Wpc, Wn, Wnc, out, n);
}